// round 14
// baseline (speedup 1.0000x reference)
#include <cuda_runtime.h>
#include <cuda.h>
#include <math.h>
#include <string.h>

// Problem constants
#define SS        26
#define CC        80
#define CELLS     676        // 26*26
#define NB        32
#define BIMG      256
#define OBJCELLS  2028       // 3*676
#define NWORDS    (OBJCELLS/4)   // 507 float4 words
#define NCH       255        // 3*(5+80)
#define DIV       16.0f      // 416/26
#define INV_IMG   (1.0f/416.0f)
#define NTHR      128
#define NSLICE    4
#define GRID      (BIMG*NSLICE)   // 1024
#define WPS       127             // noobj float4 words per slice
#define TROWS     85              // channel rows per box tile
#define TCELLS    8               // cells per tile row (32B = TMA min)
#define TILE_F    (TROWS*TCELLS)  // 680 floats transferred per box tile
#define TILE_B    (TILE_F*4)      // 2720 bytes transferred
#define TSTRIDE_F 704             // padded stride in floats: 2816 B = 22*128 (alignment!)
#define TSTRIDE_B (TSTRIDE_F*4)

__constant__ float c_anchor[18] = {
    10.f,13.f, 16.f,30.f, 33.f,23.f, 30.f,61.f, 62.f,45.f,
    59.f,119.f, 116.f,90.f, 156.f,198.f, 373.f,326.f
};

__device__ float g_partial[GRID];
__device__ unsigned int g_done_count = 0;

// ---------- helpers ----------
__device__ __forceinline__ unsigned long long mk_policy() {
    unsigned long long pol;
    asm volatile("createpolicy.fractional.L2::evict_last.b64 %0, 1.0;" : "=l"(pol));
    return pol;
}
__device__ __forceinline__ float ldg_el(const float* p, unsigned long long pol) {
    float v;
    asm volatile("ld.global.nc.L2::cache_hint.f32 %0, [%1], %2;"
                 : "=f"(v) : "l"(p), "l"(pol));
    return v;
}
__device__ __forceinline__ float4 ldg_el4(const float* p, unsigned long long pol) {
    float4 v;
    asm volatile("ld.global.nc.L2::cache_hint.v4.f32 {%0,%1,%2,%3}, [%4], %5;"
                 : "=f"(v.x), "=f"(v.y), "=f"(v.z), "=f"(v.w) : "l"(p), "l"(pol));
    return v;
}
__device__ __forceinline__ unsigned int s2u(const void* p) {
    unsigned int a;
    asm("{ .reg .u64 t; cvta.to.shared.u64 t, %1; cvt.u32.u64 %0, t; }"
        : "=r"(a) : "l"(p));
    return a;
}
__device__ __forceinline__ void mbar_init(unsigned int a, unsigned int cnt) {
    asm volatile("mbarrier.init.shared.b64 [%0], %1;" :: "r"(a), "r"(cnt) : "memory");
}
__device__ __forceinline__ void mbar_expect_tx(unsigned int a, unsigned int bytes) {
    asm volatile("mbarrier.arrive.expect_tx.shared.b64 _, [%0], %1;"
                 :: "r"(a), "r"(bytes) : "memory");
}
__device__ __forceinline__ void mbar_wait(unsigned int a, unsigned int parity) {
    asm volatile(
        "{\n\t.reg .pred P;\n\t"
        "WL_%=:\n\t"
        "mbarrier.try_wait.parity.acquire.cta.shared::cta.b64 P, [%0], %1, 0x989680;\n\t"
        "@P bra.uni WD_%=;\n\t"
        "bra.uni WL_%=;\n\t"
        "WD_%=:\n\t}"
        :: "r"(a), "r"(parity) : "memory");
}
__device__ __forceinline__ void tma_load_3d(unsigned int smem_dst, const void* tmap,
                                            int c0, int c1, int c2, unsigned int mbar) {
    asm volatile(
        "cp.async.bulk.tensor.3d.shared::cta.global.tile.mbarrier::complete_tx::bytes "
        "[%0], [%1, {%2, %3, %4}], [%5];"
        :: "r"(smem_dst), "l"(tmap), "r"(c0), "r"(c1), "r"(c2), "r"(mbar)
        : "memory");
}

// =====================================================================
// TMA kernel: per quarter-slice block, one TMA box-tile per box (8 boxes)
// =====================================================================
__global__ void __launch_bounds__(NTHR)
yolo_tma_kernel(const __grid_constant__ CUtensorMap tmap,
                const float* __restrict__ bx,
                const float* __restrict__ bbox,
                const int*   __restrict__ bidx,
                float* __restrict__ out)
{
    const int blk  = blockIdx.x;
    const int b    = blk >> 2;
    const int s    = blk & 3;
    const int tid  = threadIdx.x;
    const int warp = tid >> 5;
    const int lane = tid & 31;
    const float* __restrict__ x = bx + (size_t)b * NCH * CELLS;
    const unsigned long long pol = mk_policy();

    __shared__ __align__(128) float tile[8 * TSTRIDE_F];   // 22528 B, each tile 128B-aligned
    __shared__ __align__(8) unsigned long long mbar;
    __shared__ int   s_oa[8], s_b85[8];
    __shared__ float sredA[4];
    __shared__ float sredN[4];
    __shared__ int   s_cnt;
    __shared__ int   s_last;

    // ---- own box geometry: box k = tid>>4, classes c0 = (tid&15)*5 ----
    const int k  = tid >> 4;
    const int bi = s * 8 + k;
    const int c0 = (tid & 15) * 5;
    const bool is_head = (tid & 15) == 0;

    const float* bp = bbox + ((size_t)b * NB + bi) * 5;
    float cls = bp[0], cx = bp[1], cy = bp[2];
    int nidx = bidx[b * NB + bi];
    int base = (nidx - 3) * 85;
    int ix = (int)(cx / DIV);
    int iy = (int)(cy / DIV);
    int o  = ix * SS + iy;
    int oa = o & ~7;               // 8-cell (32B) aligned tile start
    int doff = o - oa;
    int cls_i = (int)cls;

    if (is_head) { s_oa[k] = oa; s_b85[k] = base; }
    if (tid == 0) mbar_init(s2u(&mbar), 1);
    __syncthreads();

    // ---- issue 8 TMA tile loads (thread 0) ----
    if (tid == 0) {
        unsigned int mb = s2u(&mbar);
        mbar_expect_tx(mb, 8 * TILE_B);
        unsigned int td = s2u(tile);
        #pragma unroll
        for (int kk = 0; kk < 8; kk++)
            tma_load_3d(td + kk * TSTRIDE_B, &tmap, s_oa[kk], s_b85[kk], b, mb);
    }

    // ---- overlap: noobj float4 LDGs (coalesced) ----
    float4 nv = make_float4(0.f, 0.f, 0.f, 0.f);
    const int j4 = s * WPS + tid;
    const bool has_no = (tid < WPS) && (j4 < NWORDS);
    if (has_no) {
        int r    = j4 / (CELLS / 4);
        int rem4 = j4 - r * (CELLS / 4);
        nv = ldg_el4(x + (size_t)(r * 85) * CELLS + rem4 * 4, pol);
    }
    float no = nv.x * nv.x + nv.y * nv.y + nv.z * nv.z + nv.w * nv.w;

    // ---- overlap: warp 0 dedup over all 32 boxes of the image ----
    int n_uniq = 0;
    if (warp == 0) {
        const float* mp = bbox + ((size_t)b * NB + lane) * 5;
        float mcx = mp[1], mcy = mp[2];
        int mnow = bidx[b * NB + lane] - 3;
        int mix = (int)(mcx / DIV);
        int miy = (int)(mcy / DIV);
        int m_o = mix * SS + miy;
        float ov = ldg_el(x + (size_t)(mnow * 85) * CELLS + m_o, pol);

        int cell = mnow * CELLS + m_o;
        unsigned int match = __match_any_sync(0xFFFFFFFFu, cell);
        bool is_uniq = (lane == (__ffs(match) - 1));
        n_uniq = __popc(__ballot_sync(0xFFFFFFFFu, is_uniq));
        if (is_uniq) no -= 0.25f * ov * ov;   // 4 slices each subtract 1/4
    }

    // ---- wait for tiles ----
    mbar_wait(s2u(&mbar), 0);

    // ---- label MSE from SMEM tile ----
    const float* tk = tile + k * TSTRIDE_F;
    float acc;
    {
        float v0 = tk[(5 + c0 + 0) * TCELLS + doff];
        float v1 = tk[(5 + c0 + 1) * TCELLS + doff];
        float v2 = tk[(5 + c0 + 2) * TCELLS + doff];
        float v3 = tk[(5 + c0 + 3) * TCELLS + doff];
        float v4 = tk[(5 + c0 + 4) * TCELLS + doff];
        float h0 = (c0 + 0 == cls_i) ? 1.0f : 0.0f;
        float h1 = (c0 + 1 == cls_i) ? 1.0f : 0.0f;
        float h2 = (c0 + 2 == cls_i) ? 1.0f : 0.0f;
        float h3 = (c0 + 3 == cls_i) ? 1.0f : 0.0f;
        float h4 = (c0 + 4 == cls_i) ? 1.0f : 0.0f;
        float d0 = v0 - h0, d1 = v1 - h1, d2 = v2 - h2, d3 = v3 - h3, d4 = v4 - h4;
        acc = (d0*d0 + d1*d1 + d2*d2 + d3*d3 + d4*d4) * (1.0f / (NB * CC));
    }

    // ---- coord/obj loss: this slice's 8 boxes, heads from SMEM ----
    if (is_head) {
        float obj_pred = tk[0 * TCELLS + doff];
        float rax      = tk[1 * TCELLS + doff];
        float ray      = tk[2 * TCELLS + doff];
        float t3       = tk[3 * TCELLS + doff];
        float t4       = tk[4 * TCELLS + doff];
        float bw = bp[3], bh = bp[4];

        float ax = (cx - (float)ix * DIV) / DIV;
        float ay = (cy - (float)iy * DIV) / DIV;

        float sig3 = 1.0f / (1.0f + __expf(-t3));
        float sig4 = 1.0f / (1.0f + __expf(-t4));
        float rw = c_anchor[nidx * 2 + 0] * __expf(4.0f * sig3 - 2.0f);
        float rh = c_anchor[nidx * 2 + 1] * __expf(4.0f * sig4 - 2.0f);

        float b1x0 = rax * DIV - rw * 0.5f, b1y0 = ray * DIV - rh * 0.5f;
        float b1x1 = rax * DIV + rw * 0.5f, b1y1 = ray * DIV + rh * 0.5f;
        float b2x0 = ax  * DIV - bw * 0.5f, b2y0 = ay  * DIV - bh * 0.5f;
        float b2x1 = ax  * DIV + bw * 0.5f, b2y1 = ay  * DIV + bh * 0.5f;

        float A  = (b1x1 - b1x0 + 1.0f) * (b1y1 - b1y0 + 1.0f);
        float Bt = (b2x1 - b2x0 + 1.0f) * (b2y1 - b2y0 + 1.0f);
        float CM = (fminf(b1x1, b2x1) - fmaxf(b1x0, b2x0) + 1.0f)
                 * (fminf(b1y1, b2y1) - fmaxf(b1y0, b2y0) + 1.0f);
        float iou = CM / (A + Bt - CM);
        iou = (iou < 0.0f) ? 0.0f : iou;

        float e0 = obj_pred - iou;
        float e1 = rax - ax;
        float e2 = ray - ay;
        float e3 = (rw - bw) * INV_IMG;
        float e4 = (rh - bh) * INV_IMG;

        acc += 5.0f * (e0*e0 + e1*e1 + e2*e2 + e3*e3 + e4*e4) * (1.0f / NB);
    }

    // ---- deterministic shuffle reduction over 4 warps ----
    #pragma unroll
    for (int off = 16; off > 0; off >>= 1) {
        acc += __shfl_down_sync(0xFFFFFFFFu, acc, off);
        no  += __shfl_down_sync(0xFFFFFFFFu, no,  off);
    }
    if (lane == 0) {
        sredA[warp] = acc;
        sredN[warp] = no;
        if (warp == 0) s_cnt = n_uniq;
    }
    __syncthreads();

    if (tid == 0) {
        float A  = sredA[0] + sredA[1] + sredA[2] + sredA[3];
        float Nn = sredN[0] + sredN[1] + sredN[2] + sredN[3];
        float cnt = (float)(OBJCELLS - s_cnt);
        g_partial[blk] = A + 0.5f * Nn / cnt;
        __threadfence();
        unsigned int old = atomicAdd(&g_done_count, 1u);
        s_last = (old == GRID - 1) ? 1 : 0;
    }
    __syncthreads();

    if (s_last) {
        float v = 0.0f;
        #pragma unroll
        for (int kk = 0; kk < GRID / NTHR; kk++)
            v += g_partial[tid + kk * NTHR];
        #pragma unroll
        for (int off = 16; off > 0; off >>= 1)
            v += __shfl_down_sync(0xFFFFFFFFu, v, off);
        if (lane == 0) sredA[warp] = v;
        __syncthreads();
        if (tid == 0) {
            out[0] = sredA[0] + sredA[1] + sredA[2] + sredA[3];
            atomicExch(&g_done_count, 0u);
        }
    }
}

// =====================================================================
// Fallback: proven R11 LDG kernel (launched if tensormap path unavailable)
// =====================================================================
__global__ void __launch_bounds__(NTHR)
yolo_nomask_kernel(const float* __restrict__ bx,
                   const float* __restrict__ bbox,
                   const int*   __restrict__ bidx,
                   float* __restrict__ out)
{
    const int blk  = blockIdx.x;
    const int b    = blk >> 2;
    const int s    = blk & 3;
    const int tid  = threadIdx.x;
    const int warp = tid >> 5;
    const int lane = tid & 31;
    const float* __restrict__ x = bx + (size_t)b * NCH * CELLS;
    const unsigned long long pol = mk_policy();

    __shared__ float sredA[4];
    __shared__ float sredN[4];
    __shared__ int   s_cnt;
    __shared__ int   s_last;

    const int bi = s * 8 + (tid >> 4);
    const int c0 = (tid & 15) * 5;
    const bool is_head = (tid & 15) == 0;

    const float* bp = bbox + ((size_t)b * NB + bi) * 5;
    float cls = bp[0], cx = bp[1], cy = bp[2], w = bp[3], h = bp[4];
    int nidx = bidx[b * NB + bi];
    int base = (nidx - 3) * 85;
    int ix = (int)(cx / DIV);
    int iy = (int)(cy / DIV);
    float ax = (cx - (float)ix * DIV) / DIV;
    float ay = (cy - (float)iy * DIV) / DIV;
    int o = ix * SS + iy;
    int cls_i = (int)cls;

    const float* p = x + (size_t)base * CELLS + o;

    float subsq = 0.0f;
    int   n_uniq = 0;
    if (warp == 0) {
        const float* mp = bbox + ((size_t)b * NB + lane) * 5;
        float mcx = mp[1], mcy = mp[2];
        int mnow = bidx[b * NB + lane] - 3;
        int mix = (int)(mcx / DIV);
        int miy = (int)(mcy / DIV);
        int m_o = mix * SS + miy;
        int m_cell = mnow * CELLS + m_o;

        unsigned int match = __match_any_sync(0xFFFFFFFFu, m_cell);
        bool is_uniq = (lane == (__ffs(match) - 1));
        n_uniq = __popc(__ballot_sync(0xFFFFFFFFu, is_uniq));
        if (is_uniq) {
            float ov = ldg_el(x + (size_t)(mnow * 85) * CELLS + m_o, pol);
            subsq = ov * ov;
        }
    }

    float v0 = ldg_el(p + (size_t)(5 + c0 + 0) * CELLS, pol);
    float v1 = ldg_el(p + (size_t)(5 + c0 + 1) * CELLS, pol);
    float v2 = ldg_el(p + (size_t)(5 + c0 + 2) * CELLS, pol);
    float v3 = ldg_el(p + (size_t)(5 + c0 + 3) * CELLS, pol);
    float v4 = ldg_el(p + (size_t)(5 + c0 + 4) * CELLS, pol);

    float obj_pred = 0.f, rax = 0.f, ray = 0.f, t3 = 0.f, t4 = 0.f;
    if (is_head) {
        obj_pred = ldg_el(p + 0 * CELLS, pol);
        rax      = ldg_el(p + 1 * CELLS, pol);
        ray      = ldg_el(p + 2 * CELLS, pol);
        t3       = ldg_el(p + 3 * CELLS, pol);
        t4       = ldg_el(p + 4 * CELLS, pol);
    }

    float4 nv = make_float4(0.f, 0.f, 0.f, 0.f);
    const int j4 = s * WPS + tid;
    const bool has_no = (tid < WPS) && (j4 < NWORDS);
    if (has_no) {
        int r    = j4 / (CELLS / 4);
        int rem4 = j4 - r * (CELLS / 4);
        nv = ldg_el4(x + (size_t)(r * 85) * CELLS + rem4 * 4, pol);
    }

    float acc;
    {
        float h0 = (c0 + 0 == cls_i) ? 1.0f : 0.0f;
        float h1 = (c0 + 1 == cls_i) ? 1.0f : 0.0f;
        float h2 = (c0 + 2 == cls_i) ? 1.0f : 0.0f;
        float h3 = (c0 + 3 == cls_i) ? 1.0f : 0.0f;
        float h4 = (c0 + 4 == cls_i) ? 1.0f : 0.0f;
        float d0 = v0 - h0, d1 = v1 - h1, d2 = v2 - h2, d3 = v3 - h3, d4 = v4 - h4;
        acc = (d0*d0 + d1*d1 + d2*d2 + d3*d3 + d4*d4) * (1.0f / (NB * CC));
    }

    if (is_head) {
        float sig3 = 1.0f / (1.0f + __expf(-t3));
        float sig4 = 1.0f / (1.0f + __expf(-t4));
        float rw = c_anchor[nidx * 2 + 0] * __expf(4.0f * sig3 - 2.0f);
        float rh = c_anchor[nidx * 2 + 1] * __expf(4.0f * sig4 - 2.0f);

        float b1x0 = rax * DIV - rw * 0.5f, b1y0 = ray * DIV - rh * 0.5f;
        float b1x1 = rax * DIV + rw * 0.5f, b1y1 = ray * DIV + rh * 0.5f;
        float b2x0 = ax  * DIV - w  * 0.5f, b2y0 = ay  * DIV - h  * 0.5f;
        float b2x1 = ax  * DIV + w  * 0.5f, b2y1 = ay  * DIV + h  * 0.5f;

        float A  = (b1x1 - b1x0 + 1.0f) * (b1y1 - b1y0 + 1.0f);
        float Bt = (b2x1 - b2x0 + 1.0f) * (b2y1 - b2y0 + 1.0f);
        float CM = (fminf(b1x1, b2x1) - fmaxf(b1x0, b2x0) + 1.0f)
                 * (fminf(b1y1, b2y1) - fmaxf(b1y0, b2y0) + 1.0f);
        float iou = CM / (A + Bt - CM);
        iou = (iou < 0.0f) ? 0.0f : iou;

        float e0 = obj_pred - iou;
        float e1 = rax - ax;
        float e2 = ray - ay;
        float e3 = (rw - w) * INV_IMG;
        float e4 = (rh - h) * INV_IMG;

        acc += 5.0f * (e0*e0 + e1*e1 + e2*e2 + e3*e3 + e4*e4) * (1.0f / NB);
    }

    float no = nv.x * nv.x + nv.y * nv.y + nv.z * nv.z + nv.w * nv.w;
    no -= 0.25f * subsq;

    #pragma unroll
    for (int off = 16; off > 0; off >>= 1) {
        acc += __shfl_down_sync(0xFFFFFFFFu, acc, off);
        no  += __shfl_down_sync(0xFFFFFFFFu, no,  off);
    }
    if (lane == 0) {
        sredA[warp] = acc;
        sredN[warp] = no;
        if (warp == 0) s_cnt = n_uniq;
    }
    __syncthreads();

    if (tid == 0) {
        float A  = sredA[0] + sredA[1] + sredA[2] + sredA[3];
        float Nn = sredN[0] + sredN[1] + sredN[2] + sredN[3];
        float cnt = (float)(OBJCELLS - s_cnt);
        g_partial[blk] = A + 0.5f * Nn / cnt;
        __threadfence();
        unsigned int old = atomicAdd(&g_done_count, 1u);
        s_last = (old == GRID - 1) ? 1 : 0;
    }
    __syncthreads();

    if (s_last) {
        float v = 0.0f;
        #pragma unroll
        for (int kk = 0; kk < GRID / NTHR; kk++)
            v += g_partial[tid + kk * NTHR];
        #pragma unroll
        for (int off = 16; off > 0; off >>= 1)
            v += __shfl_down_sync(0xFFFFFFFFu, v, off);
        if (lane == 0) sredA[warp] = v;
        __syncthreads();
        if (tid == 0) {
            out[0] = sredA[0] + sredA[1] + sredA[2] + sredA[3];
            atomicExch(&g_done_count, 0u);
        }
    }
}

// ---------- host ----------
typedef CUresult (*PFN_tme)(CUtensorMap*, CUtensorMapDataType, cuuint32_t, void*,
                            const cuuint64_t*, const cuuint64_t*, const cuuint32_t*,
                            const cuuint32_t*, CUtensorMapInterleave, CUtensorMapSwizzle,
                            CUtensorMapL2promotion, CUtensorMapFloatOOBfill);

extern "C" void kernel_launch(void* const* d_in, const int* in_sizes, int n_in,
                              void* d_out, int out_size)
{
    const float* bx   = (const float*)d_in[0];
    const float* bbox = (const float*)d_in[1];
    const int*   bidx = (const int*)d_in[2];
    float* out = (float*)d_out;

    void* fn = nullptr;
    cudaDriverEntryPointQueryResult qr;
    cudaError_t e = cudaGetDriverEntryPointByVersion(
        "cuTensorMapEncodeTiled", &fn, 12000, cudaEnableDefault, &qr);
    bool ok = (e == cudaSuccess) && (fn != nullptr);

    alignas(64) CUtensorMap tm;
    if (ok) {
        cuuint64_t dims[3]    = {CELLS, NCH, BIMG};
        cuuint64_t strides[2] = {(cuuint64_t)CELLS * 4ull,
                                 (cuuint64_t)CELLS * NCH * 4ull};
        cuuint32_t box[3]     = {TCELLS, TROWS, 1};
        cuuint32_t es[3]      = {1, 1, 1};
        CUresult r = ((PFN_tme)fn)(&tm, CU_TENSOR_MAP_DATA_TYPE_FLOAT32, 3,
                                   (void*)bx, dims, strides, box, es,
                                   CU_TENSOR_MAP_INTERLEAVE_NONE,
                                   CU_TENSOR_MAP_SWIZZLE_NONE,
                                   CU_TENSOR_MAP_L2_PROMOTION_L2_128B,
                                   CU_TENSOR_MAP_FLOAT_OOB_FILL_NONE);
        ok = (r == CUDA_SUCCESS);
    }

    if (ok)
        yolo_tma_kernel<<<GRID, NTHR>>>(tm, bx, bbox, bidx, out);
    else
        yolo_nomask_kernel<<<GRID, NTHR>>>(bx, bbox, bidx, out);
}

// round 15
// speedup vs baseline: 1.0025x; 1.0025x over previous
#include <cuda_runtime.h>
#include <math.h>

// Problem constants
#define SS        26
#define CC        80
#define CELLS     676        // 26*26
#define NB        32
#define BIMG      256
#define OBJCELLS  2028       // 3*676
#define NWORDS    (OBJCELLS/4)   // 507 float4 words
#define NCH       255        // 3*(5+80)
#define DIV       16.0f      // 416/26
#define INV_IMG   (1.0f/416.0f)
#define NTHR      128
#define NSLICE    4
#define GRID      (BIMG*NSLICE)   // 1024
#define WPS       127             // noobj float4 words per slice

__constant__ float c_anchor[18] = {
    10.f,13.f, 16.f,30.f, 33.f,23.f, 30.f,61.f, 62.f,45.f,
    59.f,119.f, 116.f,90.f, 156.f,198.f, 373.f,326.f
};

__device__ float g_partial[GRID];
__device__ float g_img_loss[BIMG];
__device__ unsigned int g_done_img[BIMG];
__device__ unsigned int g_done_count = 0;

// L2 evict_last via cache-policy register
__device__ __forceinline__ unsigned long long mk_policy() {
    unsigned long long pol;
    asm volatile("createpolicy.fractional.L2::evict_last.b64 %0, 1.0;" : "=l"(pol));
    return pol;
}
__device__ __forceinline__ float ldg_el(const float* p, unsigned long long pol) {
    float v;
    asm volatile("ld.global.nc.L2::cache_hint.f32 %0, [%1], %2;"
                 : "=f"(v) : "l"(p), "l"(pol));
    return v;
}
__device__ __forceinline__ float4 ldg_el4(const float* p, unsigned long long pol) {
    float4 v;
    asm volatile("ld.global.nc.L2::cache_hint.v4.f32 {%0,%1,%2,%3}, [%4], %5;"
                 : "=f"(v.x), "=f"(v.y), "=f"(v.z), "=f"(v.w) : "l"(p), "l"(pol));
    return v;
}

__global__ void __launch_bounds__(NTHR)
yolo_tree_kernel(const float* __restrict__ bx,
                 const float* __restrict__ bbox,
                 const int*   __restrict__ bidx,
                 float* __restrict__ out)
{
    const int blk  = blockIdx.x;
    const int b    = blk >> 2;       // image
    const int s    = blk & 3;        // slice
    const int tid  = threadIdx.x;
    const int warp = tid >> 5;
    const int lane = tid & 31;
    const float* __restrict__ x = bx + (size_t)b * NCH * CELLS;
    const unsigned long long pol = mk_policy();

    __shared__ float sredA[4];
    __shared__ float sredN[4];
    __shared__ int   s_cnt;
    __shared__ int   s_last;

    // ---- own box geometry: box bi = s*8 + (tid>>4), classes c0 = (tid&15)*5 ----
    const int bi = s * 8 + (tid >> 4);
    const int c0 = (tid & 15) * 5;
    const bool is_head = (tid & 15) == 0;

    const float* bp = bbox + ((size_t)b * NB + bi) * 5;
    float cls = bp[0], cx = bp[1], cy = bp[2], w = bp[3], h = bp[4];
    int nidx = bidx[b * NB + bi];
    int base = (nidx - 3) * 85;
    int ix = (int)(cx / DIV);
    int iy = (int)(cy / DIV);
    float ax = (cx - (float)ix * DIV) / DIV;
    float ay = (cy - (float)iy * DIV) / DIV;
    int o = ix * SS + iy;
    int cls_i = (int)cls;

    const float* p = x + (size_t)base * CELLS + o;

    // ---- warp 0: per-image dedup via match_any + noobj subtraction term ----
    float subsq = 0.0f;
    int   n_uniq = 0;
    if (warp == 0) {
        const float* mp = bbox + ((size_t)b * NB + lane) * 5;
        float mcx = mp[1], mcy = mp[2];
        int mnow = bidx[b * NB + lane] - 3;
        int mix = (int)(mcx / DIV);
        int miy = (int)(mcy / DIV);
        int m_o = mix * SS + miy;
        int m_cell = mnow * CELLS + m_o;

        unsigned int match = __match_any_sync(0xFFFFFFFFu, m_cell);
        bool is_uniq = (lane == (__ffs(match) - 1));
        n_uniq = __popc(__ballot_sync(0xFFFFFFFFu, is_uniq));
        if (is_uniq) {
            float ov = ldg_el(x + (size_t)(mnow * 85) * CELLS + m_o, pol);
            subsq = ov * ov;
        }
    }

    // ---- issue ALL gathers up front, fully overlapped ----
    float v0 = ldg_el(p + (size_t)(5 + c0 + 0) * CELLS, pol);
    float v1 = ldg_el(p + (size_t)(5 + c0 + 1) * CELLS, pol);
    float v2 = ldg_el(p + (size_t)(5 + c0 + 2) * CELLS, pol);
    float v3 = ldg_el(p + (size_t)(5 + c0 + 3) * CELLS, pol);
    float v4 = ldg_el(p + (size_t)(5 + c0 + 4) * CELLS, pol);

    float obj_pred = 0.f, rax = 0.f, ray = 0.f, t3 = 0.f, t4 = 0.f;
    if (is_head) {
        obj_pred = ldg_el(p + 0 * CELLS, pol);
        rax      = ldg_el(p + 1 * CELLS, pol);
        ray      = ldg_el(p + 2 * CELLS, pol);
        t3       = ldg_el(p + 3 * CELLS, pol);
        t4       = ldg_el(p + 4 * CELLS, pol);
    }

    float4 nv = make_float4(0.f, 0.f, 0.f, 0.f);
    const int j4 = s * WPS + tid;
    const bool has_no = (tid < WPS) && (j4 < NWORDS);
    if (has_no) {
        int r    = j4 / (CELLS / 4);
        int rem4 = j4 - r * (CELLS / 4);
        nv = ldg_el4(x + (size_t)(r * 85) * CELLS + rem4 * 4, pol);
    }

    // ---- label MSE ----
    float acc;
    {
        float h0 = (c0 + 0 == cls_i) ? 1.0f : 0.0f;
        float h1 = (c0 + 1 == cls_i) ? 1.0f : 0.0f;
        float h2 = (c0 + 2 == cls_i) ? 1.0f : 0.0f;
        float h3 = (c0 + 3 == cls_i) ? 1.0f : 0.0f;
        float h4 = (c0 + 4 == cls_i) ? 1.0f : 0.0f;
        float d0 = v0 - h0, d1 = v1 - h1, d2 = v2 - h2, d3 = v3 - h3, d4 = v4 - h4;
        acc = (d0*d0 + d1*d1 + d2*d2 + d3*d3 + d4*d4) * (1.0f / (NB * CC));
    }

    // ---- coord/obj loss on this slice's 8 head threads ----
    if (is_head) {
        float sig3 = 1.0f / (1.0f + __expf(-t3));
        float sig4 = 1.0f / (1.0f + __expf(-t4));
        float rw = c_anchor[nidx * 2 + 0] * __expf(4.0f * sig3 - 2.0f);
        float rh = c_anchor[nidx * 2 + 1] * __expf(4.0f * sig4 - 2.0f);

        float b1x0 = rax * DIV - rw * 0.5f, b1y0 = ray * DIV - rh * 0.5f;
        float b1x1 = rax * DIV + rw * 0.5f, b1y1 = ray * DIV + rh * 0.5f;
        float b2x0 = ax  * DIV - w  * 0.5f, b2y0 = ay  * DIV - h  * 0.5f;
        float b2x1 = ax  * DIV + w  * 0.5f, b2y1 = ay  * DIV + h  * 0.5f;

        float A  = (b1x1 - b1x0 + 1.0f) * (b1y1 - b1y0 + 1.0f);
        float Bt = (b2x1 - b2x0 + 1.0f) * (b2y1 - b2y0 + 1.0f);
        float CM = (fminf(b1x1, b2x1) - fmaxf(b1x0, b2x0) + 1.0f)
                 * (fminf(b1y1, b2y1) - fmaxf(b1y0, b2y0) + 1.0f);
        float iou = CM / (A + Bt - CM);
        iou = (iou < 0.0f) ? 0.0f : iou;

        float e0 = obj_pred - iou;
        float e1 = rax - ax;
        float e2 = ray - ay;
        float e3 = (rw - w) * INV_IMG;
        float e4 = (rh - h) * INV_IMG;

        acc += 5.0f * (e0*e0 + e1*e1 + e2*e2 + e3*e3 + e4*e4) * (1.0f / NB);
    }

    // ---- noobj row sum; unique-cell squares subtracted (x0.25, 4 slices sum to 1x) ----
    float no = nv.x * nv.x + nv.y * nv.y + nv.z * nv.z + nv.w * nv.w;
    no -= 0.25f * subsq;

    // ---- deterministic shuffle reduction over 4 warps ----
    #pragma unroll
    for (int off = 16; off > 0; off >>= 1) {
        acc += __shfl_down_sync(0xFFFFFFFFu, acc, off);
        no  += __shfl_down_sync(0xFFFFFFFFu, no,  off);
    }
    if (lane == 0) {
        sredA[warp] = acc;
        sredN[warp] = no;
        if (warp == 0) s_cnt = n_uniq;
    }
    __syncthreads();

    // ---- two-level completion tree ----
    if (tid == 0) {
        float A  = sredA[0] + sredA[1] + sredA[2] + sredA[3];
        float Nn = sredN[0] + sredN[1] + sredN[2] + sredN[3];
        float cnt = (float)(OBJCELLS - s_cnt);
        g_partial[blk] = A + 0.5f * Nn / cnt;
        __threadfence();

        int last_flag = 0;
        // level 1: per-image counter (256 independent addresses, parallel)
        unsigned int oi = atomicAdd(&g_done_img[b], 1u);
        if (oi == NSLICE - 1) {
            __threadfence();   // make other slices' partials visible
            float img = g_partial[b * 4 + 0] + g_partial[b * 4 + 1]
                      + g_partial[b * 4 + 2] + g_partial[b * 4 + 3];
            g_img_loss[b] = img;
            atomicExch(&g_done_img[b], 0u);   // reset for next replay
            __threadfence();
            // level 2: global counter (only 256 single-address ops)
            unsigned int og = atomicAdd(&g_done_count, 1u);
            last_flag = (og == BIMG - 1) ? 1 : 0;
        }
        s_last = last_flag;
    }
    __syncthreads();

    // ---- last image-finalizer block: deterministic final sum of 256 image losses ----
    if (s_last) {
        float v = g_img_loss[tid] + g_img_loss[tid + NTHR];
        #pragma unroll
        for (int off = 16; off > 0; off >>= 1)
            v += __shfl_down_sync(0xFFFFFFFFu, v, off);
        if (lane == 0) sredA[warp] = v;
        __syncthreads();
        if (tid == 0) {
            out[0] = sredA[0] + sredA[1] + sredA[2] + sredA[3];
            atomicExch(&g_done_count, 0u);   // reset for next replay
        }
    }
}

extern "C" void kernel_launch(void* const* d_in, const int* in_sizes, int n_in,
                              void* d_out, int out_size)
{
    const float* bx   = (const float*)d_in[0];
    const float* bbox = (const float*)d_in[1];
    const int*   bidx = (const int*)d_in[2];
    float* out = (float*)d_out;

    yolo_tree_kernel<<<GRID, NTHR>>>(bx, bbox, bidx, out);
}

// round 16
// speedup vs baseline: 1.1905x; 1.1875x over previous
#include <cuda_runtime.h>
#include <math.h>

// Problem constants
#define SS        26
#define CC        80
#define CELLS     676        // 26*26
#define NB        32
#define BIMG      256
#define OBJCELLS  2028       // 3*676
#define NWORDS    (OBJCELLS/4)   // 507 float4 words
#define NCH       255        // 3*(5+80)
#define DIV       16.0f      // 416/26
#define INV_IMG   (1.0f/416.0f)
#define NTHR      128
#define NSLICE    4
#define GRID      (BIMG*NSLICE)   // 1024
#define WPS       127             // noobj float4 words per slice (last gets 126)

__constant__ float c_anchor[18] = {
    10.f,13.f, 16.f,30.f, 33.f,23.f, 30.f,61.f, 62.f,45.f,
    59.f,119.f, 116.f,90.f, 156.f,198.f, 373.f,326.f
};

__device__ float g_partial[GRID];
__device__ unsigned int g_done_count = 0;

// L2 evict_last via cache-policy register
__device__ __forceinline__ unsigned long long mk_policy() {
    unsigned long long pol;
    asm volatile("createpolicy.fractional.L2::evict_last.b64 %0, 1.0;" : "=l"(pol));
    return pol;
}
__device__ __forceinline__ float ldg_el(const float* p, unsigned long long pol) {
    float v;
    asm volatile("ld.global.nc.L2::cache_hint.f32 %0, [%1], %2;"
                 : "=f"(v) : "l"(p), "l"(pol));
    return v;
}
__device__ __forceinline__ float4 ldg_el4(const float* p, unsigned long long pol) {
    float4 v;
    asm volatile("ld.global.nc.L2::cache_hint.v4.f32 {%0,%1,%2,%3}, [%4], %5;"
                 : "=f"(v.x), "=f"(v.y), "=f"(v.z), "=f"(v.w) : "l"(p), "l"(pol));
    return v;
}

__global__ void __launch_bounds__(NTHR)
yolo_flat4_kernel(const float* __restrict__ bx,
                  const float* __restrict__ bbox,
                  const int*   __restrict__ bidx,
                  float* __restrict__ out)
{
    const int blk  = blockIdx.x;
    const int b    = blk >> 2;       // image
    const int s    = blk & 3;        // slice
    const int tid  = threadIdx.x;
    const int warp = tid >> 5;       // 4 warps
    const int lane = tid & 31;
    const float* __restrict__ x = bx + (size_t)b * NCH * CELLS;
    const unsigned long long pol = mk_policy();

    __shared__ unsigned int cleared32[NWORDS];
    __shared__ float sredA[4];
    __shared__ float sredN[4];
    __shared__ int   sredC[4];
    __shared__ int   s_last;

    unsigned char* cleared = (unsigned char*)cleared32;

    // Zero mask: 4 words per thread
    #pragma unroll
    for (int j = tid; j < NWORDS; j += NTHR) cleared32[j] = 0u;

    // ---- Per-thread box geometry from global (own label box) ----
    // thread t -> box bi = s*8 + (t>>4), classes c0 = (t&15)*5 .. +4
    const int bi = s * 8 + (tid >> 4);
    const int c0 = (tid & 15) * 5;
    const bool is_head = (tid & 15) == 0;

    const float* bp = bbox + ((size_t)b * NB + bi) * 5;
    float cls = bp[0], cx = bp[1], cy = bp[2], w = bp[3], h = bp[4];
    int nidx = bidx[b * NB + bi];
    int base = (nidx - 3) * 85;
    int ix = (int)(cx / DIV);
    int iy = (int)(cy / DIV);
    float ax = (cx - (float)ix * DIV) / DIV;
    float ay = (cy - (float)iy * DIV) / DIV;
    int o = ix * SS + iy;
    int cls_i = (int)cls;

    const float* p = x + (size_t)base * CELLS + o;

    // ---- Mask geometry for ALL 32 boxes (threads 0..31), computed from global ----
    int m_now = 0, m_o = 0;
    if (tid < NB) {
        const float* mp = bbox + ((size_t)b * NB + tid) * 5;
        float mcx = mp[1], mcy = mp[2];
        int mnidx = bidx[b * NB + tid];
        m_now = mnidx - 3;
        int mix = (int)(mcx / DIV);
        int miy = (int)(mcy / DIV);
        m_o = mix * SS + miy;
    }

    // ---- Issue ALL gathers now (label + head + noobj), fully overlapped ----
    float v0 = ldg_el(p + (size_t)(5 + c0 + 0) * CELLS, pol);
    float v1 = ldg_el(p + (size_t)(5 + c0 + 1) * CELLS, pol);
    float v2 = ldg_el(p + (size_t)(5 + c0 + 2) * CELLS, pol);
    float v3 = ldg_el(p + (size_t)(5 + c0 + 3) * CELLS, pol);
    float v4 = ldg_el(p + (size_t)(5 + c0 + 4) * CELLS, pol);

    float obj_pred = 0.f, rax = 0.f, ray = 0.f, t3 = 0.f, t4 = 0.f;
    if (is_head) {
        obj_pred = ldg_el(p + 0 * CELLS, pol);
        rax      = ldg_el(p + 1 * CELLS, pol);
        ray      = ldg_el(p + 2 * CELLS, pol);
        t3       = ldg_el(p + 3 * CELLS, pol);
        t4       = ldg_el(p + 4 * CELLS, pol);
    }

    float4 nv = make_float4(0.f, 0.f, 0.f, 0.f);
    const int j4 = s * WPS + tid;
    const bool has_no = (tid < WPS) && (j4 < NWORDS);
    if (has_no) {
        int r    = j4 / (CELLS / 4);
        int rem4 = j4 - r * (CELLS / 4);
        nv = ldg_el4(x + (size_t)(r * 85) * CELLS + rem4 * 4, pol);
    }

    // Mask-zero fence (loads above stay in flight across the barrier)
    __syncthreads();

    // Scatter cleared flags for all 32 boxes (duplicate writes of 1 benign)
    if (tid < NB) cleared[m_now * CELLS + m_o] = 1;

    // ---- Label MSE (overlaps with scatter settling) ----
    float acc;
    {
        float hot0 = (c0 + 0 == cls_i) ? 1.0f : 0.0f;
        float hot1 = (c0 + 1 == cls_i) ? 1.0f : 0.0f;
        float hot2 = (c0 + 2 == cls_i) ? 1.0f : 0.0f;
        float hot3 = (c0 + 3 == cls_i) ? 1.0f : 0.0f;
        float hot4 = (c0 + 4 == cls_i) ? 1.0f : 0.0f;
        float d0 = v0 - hot0, d1 = v1 - hot1, d2 = v2 - hot2,
              d3 = v3 - hot3, d4 = v4 - hot4;
        acc = (d0*d0 + d1*d1 + d2*d2 + d3*d3 + d4*d4) * (1.0f / (NB * CC));
    }

    // ---- Coord/obj loss on this slice's 8 head threads ----
    if (is_head) {
        float sig3 = 1.0f / (1.0f + __expf(-t3));
        float sig4 = 1.0f / (1.0f + __expf(-t4));
        float rw = c_anchor[nidx * 2 + 0] * __expf(4.0f * sig3 - 2.0f);
        float rh = c_anchor[nidx * 2 + 1] * __expf(4.0f * sig4 - 2.0f);

        float b1x0 = rax * DIV - rw * 0.5f, b1y0 = ray * DIV - rh * 0.5f;
        float b1x1 = rax * DIV + rw * 0.5f, b1y1 = ray * DIV + rh * 0.5f;
        float b2x0 = ax  * DIV - w  * 0.5f, b2y0 = ay  * DIV - h  * 0.5f;
        float b2x1 = ax  * DIV + w  * 0.5f, b2y1 = ay  * DIV + h  * 0.5f;

        float A  = (b1x1 - b1x0 + 1.0f) * (b1y1 - b1y0 + 1.0f);
        float Bt = (b2x1 - b2x0 + 1.0f) * (b2y1 - b2y0 + 1.0f);
        float CM = (fminf(b1x1, b2x1) - fmaxf(b1x0, b2x0) + 1.0f)
                 * (fminf(b1y1, b2y1) - fmaxf(b1y0, b2y0) + 1.0f);
        float iou = CM / (A + Bt - CM);
        iou = (iou < 0.0f) ? 0.0f : iou;

        float e0 = obj_pred - iou;
        float e1 = rax - ax;
        float e2 = ray - ay;
        float e3 = (rw - w) * INV_IMG;
        float e4 = (rh - h) * INV_IMG;

        acc += 5.0f * (e0*e0 + e1*e1 + e2*e2 + e3*e3 + e4*e4) * (1.0f / NB);
    }

    // Mask-scatter fence
    __syncthreads();

    // ---- Apply mask to preloaded noobj values; full dedup count per slice ----
    float no = 0.0f;
    if (has_no) {
        unsigned int m = cleared32[j4];
        if (!(m & 0x000000FFu)) no += nv.x * nv.x;
        if (!(m & 0x0000FF00u)) no += nv.y * nv.y;
        if (!(m & 0x00FF0000u)) no += nv.z * nv.z;
        if (!(m & 0xFF000000u)) no += nv.w * nv.w;
    }
    int ccount = 0;
    #pragma unroll
    for (int j = tid; j < NWORDS; j += NTHR) ccount += __popc(cleared32[j]);

    // ---- Deterministic shuffle reduction over 4 warps ----
    #pragma unroll
    for (int off = 16; off > 0; off >>= 1) {
        acc    += __shfl_down_sync(0xFFFFFFFFu, acc,    off);
        no     += __shfl_down_sync(0xFFFFFFFFu, no,     off);
        ccount += __shfl_down_sync(0xFFFFFFFFu, ccount, off);
    }
    if (lane == 0) { sredA[warp] = acc; sredN[warp] = no; sredC[warp] = ccount; }
    __syncthreads();

    if (tid == 0) {
        float A = sredA[0] + sredA[1] + sredA[2] + sredA[3];
        float Nn = sredN[0] + sredN[1] + sredN[2] + sredN[3];
        int   Cc = sredC[0] + sredC[1] + sredC[2] + sredC[3];
        float cnt = (float)(OBJCELLS - Cc);
        g_partial[blk] = A + 0.5f * Nn / cnt;
        __threadfence();
        unsigned int old = atomicAdd(&g_done_count, 1u);
        s_last = (old == GRID - 1) ? 1 : 0;
    }
    __syncthreads();

    // ---- Last block standing: deterministic fixed-order reduction of 1024 partials ----
    if (s_last) {
        float v = 0.0f;
        #pragma unroll
        for (int k = 0; k < GRID / NTHR; k++)
            v += g_partial[tid + k * NTHR];
        #pragma unroll
        for (int off = 16; off > 0; off >>= 1)
            v += __shfl_down_sync(0xFFFFFFFFu, v, off);
        if (lane == 0) sredA[warp] = v;
        __syncthreads();
        if (tid == 0) {
            out[0] = sredA[0] + sredA[1] + sredA[2] + sredA[3];
            atomicExch(&g_done_count, 0u);   // reset for next graph replay
        }
    }
}

extern "C" void kernel_launch(void* const* d_in, const int* in_sizes, int n_in,
                              void* d_out, int out_size)
{
    const float* bx   = (const float*)d_in[0];
    const float* bbox = (const float*)d_in[1];
    const int*   bidx = (const int*)d_in[2];
    float* out = (float*)d_out;

    yolo_flat4_kernel<<<GRID, NTHR>>>(bx, bbox, bidx, out);
}